// round 9
// baseline (speedup 1.0000x reference)
#include <cuda_runtime.h>
#include <cstdint>
#include <mma.h>

using namespace nvcuda;

// ---------------------------------------------------------------------------
// MoE HyperModel, round 8: full-height (M=256) GEMM tiles so each weight
// byte is read from HBM exactly once. 3-stage cp.async ring, k-tile 32,
// single sync per tile. eo keeps the fused-h A-loader.
// ---------------------------------------------------------------------------

namespace {
constexpr int kEMB = 1024;
constexpr int kCTX = 32;
constexpr int kNE  = 16;
constexpr int kH1  = 2048;
constexpr int kH2  = 512;
constexpr int kB   = 8;
constexpr int kM   = kCTX * kB;     // 256
constexpr int kFO  = 16384;
constexpr int kW1R = kEMB + kCTX;   // 1056

constexpr int kLDA = 36;     // smem A stride: 256 rows x 32 k (+pad)
constexpr int kLDB = 132;    // smem B stride: 32 rows x 128 n (+pad)
constexpr int kAstF = 256 * kLDA;        // 9216 floats
constexpr int kBstF = 32 * kLDB;         // 4224 floats
constexpr int kStF  = kAstF + kBstF;     // 13440 floats
constexpr int kSmemGemm = 3 * kStF * 4;  // 161280 bytes
}

// Scratch (static device arrays -- allocation-free).
__device__ float g_g1[kB * kH1];
__device__ float g_w[kB * kNE];
__device__ float g_base[kNE * kB * kH1];
__device__ float g_eo2[(size_t)2 * kNE * kM * kH2];   // split-K partials
__device__ float g_z[kM * kH2];

// --------------------------- cp.async helpers ------------------------------
__device__ __forceinline__ void cp_async16(float* smem_dst, const float* gmem_src) {
    unsigned int s = (unsigned int)__cvta_generic_to_shared(smem_dst);
    asm volatile("cp.async.cg.shared.global [%0], [%1], 16;\n" :: "r"(s), "l"(gmem_src));
}
__device__ __forceinline__ void cp_commit() {
    asm volatile("cp.async.commit_group;\n");
}
template <int N>
__device__ __forceinline__ void cp_wait() {
    asm volatile("cp.async.wait_group %0;\n" :: "n"(N));
}

// --------------------------- stage loaders ---------------------------------
// B: 32 k-rows x 128 n via cp.async (B pre-offset to n0). 4 float4/thread.
__device__ __forceinline__ void load_B(float* Bs, const float* B, int ldb,
                                       int kt, int t)
{
#pragma unroll
    for (int i = 0; i < 4; i++) {
        const int id = t + i * 256;
        const int r = id >> 5, c4 = (id & 31) * 4;
        cp_async16(Bs + r * kLDB + c4, B + (size_t)(kt + r) * ldb + c4);
    }
}
// A (out GEMM): 256 rows x 32 k via cp.async from g_z. 8 float4/thread.
__device__ __forceinline__ void load_A_cp(float* As, const float* A, int lda,
                                          int kt, int t)
{
#pragma unroll
    for (int i = 0; i < 8; i++) {
        const int id = t + i * 256;
        const int m = id >> 3, kc = (id & 7) * 4;
        cp_async16(As + m * kLDA + kc, A + (size_t)m * lda + kt + kc);
    }
}
// A (eo GEMM, fused h): a = tf32( w[b] * relu(base[b][k] + W1c[c][k]) ), STS.
__device__ __forceinline__ void load_A_eo(float* As,
                                          const float* base_e, const float* w1c_e,
                                          const float* ws, int kt, int t)
{
#pragma unroll
    for (int i = 0; i < 8; i++) {
        const int id = t + i * 256;
        const int m = id >> 3, kc = (id & 7) * 4;
        const int b = m & 7, c = m >> 3;
        const float4 bs = *reinterpret_cast<const float4*>(base_e + (size_t)b * kH1 + kt + kc);
        const float4 wc = *reinterpret_cast<const float4*>(w1c_e + (size_t)c * kH1 + kt + kc);
        const float w = ws[b];
        float4 r;
        r.x = wmma::__float_to_tf32(w * fmaxf(bs.x + wc.x, 0.f));
        r.y = wmma::__float_to_tf32(w * fmaxf(bs.y + wc.y, 0.f));
        r.z = wmma::__float_to_tf32(w * fmaxf(bs.z + wc.z, 0.f));
        r.w = wmma::__float_to_tf32(w * fmaxf(bs.w + wc.w, 0.f));
        *reinterpret_cast<float4*>(As + m * kLDA + kc) = r;
    }
}

// --------------------------- compute: warp 64x64, k-tile 32 ----------------
// 8 warps: wm = warp>>1 (4 m-tiles of 64), wn = warp&1 (2 n-tiles of 64).
__device__ __forceinline__ void tile_compute(
    const float* stage, int wm, int wn,
    wmma::fragment<wmma::accumulator, 16, 16, 8, float> (&acc)[4][4])
{
    const float* As = stage;
    const float* Bs = stage + kAstF;
#pragma unroll
    for (int kk = 0; kk < 4; kk++) {
        wmma::fragment<wmma::matrix_b, 16, 16, 8, wmma::precision::tf32, wmma::row_major> bf[4];
#pragma unroll
        for (int j = 0; j < 4; j++) {
            wmma::load_matrix_sync(bf[j], Bs + (kk * 8) * kLDB + wn * 64 + j * 16, kLDB);
#pragma unroll
            for (int u = 0; u < bf[j].num_elements; u++)
                bf[j].x[u] = wmma::__float_to_tf32(bf[j].x[u]);
        }
#pragma unroll
        for (int i = 0; i < 4; i++) {
            wmma::fragment<wmma::matrix_a, 16, 16, 8, wmma::precision::tf32, wmma::row_major> af;
            wmma::load_matrix_sync(af, As + (wm * 64 + i * 16) * kLDA + kk * 8, kLDA);
#pragma unroll
            for (int j = 0; j < 4; j++)
                wmma::mma_sync(acc[i][j], af, bf[j], acc[i][j]);
        }
    }
}

// ---------------------------------------------------------------------------
// k_base: base[e,b,:] = s @ W1s[e] + b1[e]; e==16 -> gating g1 (relu).
// ---------------------------------------------------------------------------
__global__ __launch_bounds__(256) void k_base(
    const float* __restrict__ s,
    const float* __restrict__ W1, const float* __restrict__ b1,
    const float* __restrict__ Wg1, const float* __restrict__ bg1)
{
    __shared__ float ssm[kB * kEMB];
    __shared__ float red[128][kB];
    const int t = threadIdx.x;
    const int e = blockIdx.y;
    const int jl = t & 127;
    const int half = t >> 7;
    const int j = blockIdx.x * 128 + jl;

    for (int i = t; i < kB * kEMB; i += 256) ssm[i] = s[i];
    __syncthreads();

    const float* __restrict__ W = (e < kNE) ? (W1 + (size_t)e * kW1R * kH1) : Wg1;

    float acc[kB];
#pragma unroll
    for (int b = 0; b < kB; b++) acc[b] = 0.f;

    const int i0 = half * 512;
#pragma unroll 4
    for (int i = i0; i < i0 + 512; i++) {
        const float w = W[(size_t)i * kH1 + j];
#pragma unroll
        for (int b = 0; b < kB; b++) acc[b] += ssm[b * kEMB + i] * w;
    }

    if (half) {
#pragma unroll
        for (int b = 0; b < kB; b++) red[jl][b] = acc[b];
    }
    __syncthreads();
    if (!half) {
#pragma unroll
        for (int b = 0; b < kB; b++) acc[b] += red[jl][b];
        if (e < kNE) {
            const float bias = b1[e * kH1 + j];
#pragma unroll
            for (int b = 0; b < kB; b++)
                g_base[((size_t)e * kB + b) * kH1 + j] = acc[b] + bias;
        } else {
            const float bias = bg1[j];
#pragma unroll
            for (int b = 0; b < kB; b++)
                g_g1[b * kH1 + j] = fmaxf(acc[b] + bias, 0.f);
        }
    }
}

// ---------------------------------------------------------------------------
// k_gate
// ---------------------------------------------------------------------------
__global__ __launch_bounds__(1024) void k_gate(
    const float* __restrict__ Wg2, const float* __restrict__ bg2)
{
    __shared__ float red[1024];
    const int t = threadIdx.x;
    const int b = t >> 7;
    const int rem = t & 127;
    const int kc = rem >> 4;
    const int x = rem & 15;

    float acc = 0.f;
    const int j0 = kc * 256;
#pragma unroll 4
    for (int j = j0; j < j0 + 256; j++)
        acc += g_g1[b * kH1 + j] * Wg2[j * kNE + x];
    red[t] = acc;
    __syncthreads();

    if (t < 128) {
        const int bb = t >> 4;
        const int xx = t & 15;
        float a = bg2[xx];
#pragma unroll
        for (int k = 0; k < 8; k++) a += red[bb * 128 + k * 16 + xx];

        float mx = a;
#pragma unroll
        for (int o = 8; o >= 1; o >>= 1)
            mx = fmaxf(mx, __shfl_xor_sync(0xffffffffu, mx, o, 16));
        const float ev = expf(a - mx);
        float sm = ev;
#pragma unroll
        for (int o = 8; o >= 1; o >>= 1)
            sm += __shfl_xor_sync(0xffffffffu, sm, o, 16);

        g_w[bb * kNE + xx] = ev / sm;
    }
}

// ---------------------------------------------------------------------------
// k_gemm_eo: fused-h split-K per-expert GEMM, full-height tile 256x128.
// Grid: (4 ntiles, 1, 32 = expert*2 + khalf). K per CTA = 1024, 32 k-tiles.
// ---------------------------------------------------------------------------
__global__ __launch_bounds__(256) void k_gemm_eo(
    const float* __restrict__ W1, const float* __restrict__ W2)
{
    extern __shared__ float smem[];
    __shared__ float ws[kB];

    const int t = threadIdx.x;
    const int warp = t >> 5;
    const int wm = warp >> 1;   // 0..3
    const int wn = warp & 1;    // 0..1
    const int zz = blockIdx.z, e = zz >> 1, kh = zz & 1;
    const int n0 = blockIdx.x * 128;

    if (t < kB) ws[t] = g_w[t * kNE + e];

    const float* base_e = g_base + (size_t)e * kB * kH1 + kh * 1024;
    const float* w1c_e  = W1 + ((size_t)e * kW1R + kEMB) * kH1 + kh * 1024;
    const float* B      = W2 + (size_t)e * kH1 * kH2 + (size_t)(kh * 1024) * kH2 + n0;

    wmma::fragment<wmma::accumulator, 16, 16, 8, float> acc[4][4];
#pragma unroll
    for (int i = 0; i < 4; i++)
#pragma unroll
        for (int j = 0; j < 4; j++) wmma::fill_fragment(acc[i][j], 0.f);

    __syncthreads();   // ws visible

    constexpr int NT = 1024 / 32;   // 32
    // Prologue: stages 0 and 1.
    load_B(smem + kAstF, B, kH2, 0, t);
    cp_commit();
    load_A_eo(smem, base_e, w1c_e, ws, 0, t);
    load_B(smem + kStF + kAstF, B, kH2, 32, t);
    cp_commit();
    load_A_eo(smem + kStF, base_e, w1c_e, ws, 32, t);
    __syncthreads();   // A STS of stages 0,1 visible

    for (int it = 0; it < NT; it++) {
        if (it + 1 < NT) cp_wait<1>(); else cp_wait<0>();
        __syncthreads();
        if (it + 2 < NT) {
            float* nxt = smem + ((it + 2) % 3) * kStF;
            load_B(nxt + kAstF, B, kH2, (it + 2) * 32, t);
            cp_commit();
            load_A_eo(nxt, base_e, w1c_e, ws, (it + 2) * 32, t);
        }
        tile_compute(smem + (it % 3) * kStF, wm, wn, acc);
    }

    float* O = g_eo2 + (size_t)zz * kM * kH2 + n0;
#pragma unroll
    for (int i = 0; i < 4; i++)
#pragma unroll
        for (int j = 0; j < 4; j++)
            wmma::store_matrix_sync(O + (size_t)(wm * 64 + i * 16) * kH2 + wn * 64 + j * 16,
                                    acc[i][j], kH2, wmma::mem_row_major);
}

// ---------------------------------------------------------------------------
// k_z: z = tf32( sum over 32 partial slabs + sum_e w[b,e]*b2[e] ).
// ---------------------------------------------------------------------------
__global__ __launch_bounds__(256) void k_z(const float* __restrict__ b2)
{
    const int idx = blockIdx.x * 256 + threadIdx.x;
    const int n = idx & (kH2 - 1);
    const int m = idx >> 9;
    const int b = m & 7;

    float acc = 0.f;
#pragma unroll
    for (int p = 0; p < 2 * kNE; p++)
        acc += g_eo2[(size_t)p * (kM * kH2) + idx];
#pragma unroll
    for (int e = 0; e < kNE; e++)
        acc += g_w[b * kNE + e] * b2[e * kH2 + n];
    g_z[idx] = wmma::__float_to_tf32(acc);
}

// ---------------------------------------------------------------------------
// k_gemm_out: z(256x512) @ {WA,WB}(512x16384) + bias -> out.
// Full-height tile 256x128. Grid: (128 ntiles, 1, 2 mats). 16 k-tiles.
// ---------------------------------------------------------------------------
__global__ __launch_bounds__(256) void k_gemm_out(
    const float* __restrict__ WA, const float* __restrict__ bA,
    const float* __restrict__ WB, const float* __restrict__ bB,
    float* __restrict__ out)
{
    extern __shared__ float smem[];

    const int t = threadIdx.x;
    const int warp = t >> 5;
    const int wm = warp >> 1;
    const int wn = warp & 1;
    const int mat = blockIdx.z;
    const int n0 = blockIdx.x * 128;

    const float* __restrict__ Bw   = mat ? WB : WA;
    const float* __restrict__ bias = mat ? bB : bA;

    const float* A = g_z;
    const float* B = Bw + n0;

    wmma::fragment<wmma::accumulator, 16, 16, 8, float> acc[4][4];
#pragma unroll
    for (int i = 0; i < 4; i++)
#pragma unroll
        for (int j = 0; j < 4; j++) wmma::fill_fragment(acc[i][j], 0.f);

    constexpr int NT = kH2 / 32;   // 16
    load_A_cp(smem, A, kH2, 0, t);
    load_B(smem + kAstF, B, kFO, 0, t);
    cp_commit();
    load_A_cp(smem + kStF, A, kH2, 32, t);
    load_B(smem + kStF + kAstF, B, kFO, 32, t);
    cp_commit();

    for (int it = 0; it < NT; it++) {
        if (it + 1 < NT) cp_wait<1>(); else cp_wait<0>();
        __syncthreads();
        if (it + 2 < NT) {
            float* nxt = smem + ((it + 2) % 3) * kStF;
            load_A_cp(nxt, A, kH2, (it + 2) * 32, t);
            load_B(nxt + kAstF, B, kFO, (it + 2) * 32, t);
            cp_commit();
        }
        tile_compute(smem + (it % 3) * kStF, wm, wn, acc);
    }

    // Epilogue: stage 256x128 (stride 132) in smem, add bias, float4 stores.
    __syncthreads();
#pragma unroll
    for (int i = 0; i < 4; i++)
#pragma unroll
        for (int j = 0; j < 4; j++)
            wmma::store_matrix_sync(smem + (wm * 64 + i * 16) * kLDB + wn * 64 + j * 16,
                                    acc[i][j], kLDB, wmma::mem_row_major);
    __syncthreads();

    float* O = out + (size_t)mat * kM * kFO + n0;
#pragma unroll
    for (int i = 0; i < 32; i++) {
        const int id = t + i * 256;
        const int r = id >> 5, c4 = (id & 31) * 4;
        float4 v  = *reinterpret_cast<const float4*>(smem + r * kLDB + c4);
        const float4 bv = *reinterpret_cast<const float4*>(bias + n0 + c4);
        v.x += bv.x; v.y += bv.y; v.z += bv.z; v.w += bv.w;
        *reinterpret_cast<float4*>(O + (size_t)r * kFO + c4) = v;
    }
}

// ---------------------------------------------------------------------------
// kernel_launch
// ---------------------------------------------------------------------------
extern "C" void kernel_launch(void* const* d_in, const int* in_sizes, int n_in,
                              void* d_out, int out_size)
{
    const float* s   = (const float*)d_in[0];
    const float* Wg1 = (const float*)d_in[1];
    const float* bg1 = (const float*)d_in[2];
    const float* Wg2 = (const float*)d_in[3];
    const float* bg2 = (const float*)d_in[4];
    const float* W1  = (const float*)d_in[5];
    const float* b1  = (const float*)d_in[6];
    const float* W2  = (const float*)d_in[7];
    const float* b2  = (const float*)d_in[8];
    const float* WA  = (const float*)d_in[9];
    const float* bA  = (const float*)d_in[10];
    const float* WB  = (const float*)d_in[11];
    const float* bB  = (const float*)d_in[12];
    float* out = (float*)d_out;

    cudaFuncSetAttribute(k_gemm_eo,  cudaFuncAttributeMaxDynamicSharedMemorySize, kSmemGemm);
    cudaFuncSetAttribute(k_gemm_out, cudaFuncAttributeMaxDynamicSharedMemorySize, kSmemGemm);

    k_base<<<dim3(kH1 / 128, kNE + 1), 256>>>(s, W1, b1, Wg1, bg1);
    k_gate<<<1, 1024>>>(Wg2, bg2);
    k_gemm_eo<<<dim3(kH2 / 128, 1, 2 * kNE), 256, kSmemGemm>>>(W1, W2);
    k_z<<<(kM * kH2) / 256, 256>>>(b2);
    k_gemm_out<<<dim3(kFO / 128, 1, 2), 256, kSmemGemm>>>(WA, bA, WB, bB, out);
}

// round 10
// speedup vs baseline: 1.5133x; 1.5133x over previous
#include <cuda_runtime.h>
#include <cuda_fp16.h>
#include <cstdint>
#include <mma.h>

using namespace nvcuda;

// ---------------------------------------------------------------------------
// MoE HyperModel, round 9: fp16 HMMA (2x tf32 rate), fp32 accumulate.
// Weights pre-converted to fp16 once per launch; eo A fused on the fly;
// z stored as fp16. 3-stage cp.async ring, k-tile 64, full-height tiles.
// ---------------------------------------------------------------------------

namespace {
constexpr int kEMB = 1024;
constexpr int kCTX = 32;
constexpr int kNE  = 16;
constexpr int kH1  = 2048;
constexpr int kH2  = 512;
constexpr int kB   = 8;
constexpr int kM   = kCTX * kB;     // 256
constexpr int kFO  = 16384;
constexpr int kW1R = kEMB + kCTX;   // 1056

constexpr int kLDAh = 72;    // smem A stride (halves): 256 rows x 64 k (+pad)
constexpr int kLDBh = 136;   // smem B stride (halves): 64 rows x 128 n (+pad)
constexpr int kAstH = 256 * kLDAh;        // 18432 halves
constexpr int kBstH = 64 * kLDBh;         // 8704 halves
constexpr int kStH  = kAstH + kBstH;      // 27136 halves
constexpr int kSmemGemm = 3 * kStH * 2;   // 162816 bytes
}

// Scratch (static device arrays -- allocation-free).
__device__ float  g_g1[kB * kH1];
__device__ float  g_w[kB * kNE];
__device__ float  g_base[kNE * kB * kH1];
__device__ float  g_eo2[(size_t)2 * kNE * kM * kH2];        // split-K partials
__device__ __half g_zh[kM * kH2];                           // z in fp16
__device__ __half g_W2h[(size_t)kNE * kH1 * kH2];           // 33.5 MB
__device__ __half g_WAh[(size_t)kH2 * kFO];                 // 16.8 MB
__device__ __half g_WBh[(size_t)kH2 * kFO];                 // 16.8 MB

// --------------------------- cp.async helpers ------------------------------
__device__ __forceinline__ void cp_async16(void* smem_dst, const void* gmem_src) {
    unsigned int s = (unsigned int)__cvta_generic_to_shared(smem_dst);
    asm volatile("cp.async.cg.shared.global [%0], [%1], 16;\n" :: "r"(s), "l"(gmem_src));
}
__device__ __forceinline__ void cp_commit() {
    asm volatile("cp.async.commit_group;\n");
}
template <int N>
__device__ __forceinline__ void cp_wait() {
    asm volatile("cp.async.wait_group %0;\n" :: "n"(N));
}

// --------------------------- fp32 -> fp16 convert ---------------------------
__global__ __launch_bounds__(256) void k_cvt(
    const float* __restrict__ src, __half* __restrict__ dst, int n)
{
    const int i = (blockIdx.x * 256 + threadIdx.x) * 8;
    if (i < n) {
        const float4 a = *reinterpret_cast<const float4*>(src + i);
        const float4 b = *reinterpret_cast<const float4*>(src + i + 4);
        __half2 h0 = __floats2half2_rn(a.x, a.y);
        __half2 h1 = __floats2half2_rn(a.z, a.w);
        __half2 h2 = __floats2half2_rn(b.x, b.y);
        __half2 h3 = __floats2half2_rn(b.z, b.w);
        uint4 v;
        v.x = *reinterpret_cast<unsigned*>(&h0);
        v.y = *reinterpret_cast<unsigned*>(&h1);
        v.z = *reinterpret_cast<unsigned*>(&h2);
        v.w = *reinterpret_cast<unsigned*>(&h3);
        *reinterpret_cast<uint4*>(dst + i) = v;
    }
}

// --------------------------- stage loaders ---------------------------------
// B: 64 k-rows x 128 n halves via cp.async (B pre-offset to n0). 4 chunks/thr.
__device__ __forceinline__ void load_B(__half* Bs, const __half* B, int ldb,
                                       int kt, int t)
{
#pragma unroll
    for (int i = 0; i < 4; i++) {
        const int id = t + i * 256;
        const int r = id >> 4, c8 = (id & 15) * 8;
        cp_async16(Bs + r * kLDBh + c8, B + (size_t)(kt + r) * ldb + c8);
    }
}
// A (out GEMM): 256 rows x 64 k halves via cp.async from g_zh. 8 chunks/thr.
__device__ __forceinline__ void load_A_cp(__half* As, const __half* A, int lda,
                                          int kt, int t)
{
#pragma unroll
    for (int i = 0; i < 8; i++) {
        const int id = t + i * 256;
        const int m = id >> 3, kc = (id & 7) * 8;
        cp_async16(As + m * kLDAh + kc, A + (size_t)m * lda + kt + kc);
    }
}
// A (eo GEMM, fused h): half( w[b] * relu(base[b][k] + W1c[c][k]) ), STS.
__device__ __forceinline__ void load_A_eo(__half* As,
                                          const float* base_e, const float* w1c_e,
                                          const float* ws, int kt, int t)
{
#pragma unroll
    for (int i = 0; i < 8; i++) {
        const int id = t + i * 256;
        const int m = id >> 3, kc = (id & 7) * 8;
        const int b = m & 7, c = m >> 3;
        const float* bp = base_e + (size_t)b * kH1 + kt + kc;
        const float* wp = w1c_e  + (size_t)c * kH1 + kt + kc;
        const float4 b0 = *reinterpret_cast<const float4*>(bp);
        const float4 b1 = *reinterpret_cast<const float4*>(bp + 4);
        const float4 w0 = *reinterpret_cast<const float4*>(wp);
        const float4 w1 = *reinterpret_cast<const float4*>(wp + 4);
        const float w = ws[b];
        __half2 h0 = __floats2half2_rn(w * fmaxf(b0.x + w0.x, 0.f), w * fmaxf(b0.y + w0.y, 0.f));
        __half2 h1 = __floats2half2_rn(w * fmaxf(b0.z + w0.z, 0.f), w * fmaxf(b0.w + w0.w, 0.f));
        __half2 h2 = __floats2half2_rn(w * fmaxf(b1.x + w1.x, 0.f), w * fmaxf(b1.y + w1.y, 0.f));
        __half2 h3 = __floats2half2_rn(w * fmaxf(b1.z + w1.z, 0.f), w * fmaxf(b1.w + w1.w, 0.f));
        uint4 v;
        v.x = *reinterpret_cast<unsigned*>(&h0);
        v.y = *reinterpret_cast<unsigned*>(&h1);
        v.z = *reinterpret_cast<unsigned*>(&h2);
        v.w = *reinterpret_cast<unsigned*>(&h3);
        *reinterpret_cast<uint4*>(As + m * kLDAh + kc) = v;
    }
}

// --------------------------- compute: warp 64x64, k-tile 64 ----------------
// 8 warps: wm = warp>>1 (4 m-slots of 64), wn = warp&1 (2 n-slots of 64).
__device__ __forceinline__ void tile_compute(
    const __half* As, const __half* Bs, int wm, int wn,
    wmma::fragment<wmma::accumulator, 16, 16, 16, float> (&acc)[4][4])
{
#pragma unroll
    for (int kk = 0; kk < 4; kk++) {
        wmma::fragment<wmma::matrix_b, 16, 16, 16, __half, wmma::row_major> bf[4];
#pragma unroll
        for (int j = 0; j < 4; j++)
            wmma::load_matrix_sync(bf[j], Bs + (kk * 16) * kLDBh + wn * 64 + j * 16, kLDBh);
#pragma unroll
        for (int i = 0; i < 4; i++) {
            wmma::fragment<wmma::matrix_a, 16, 16, 16, __half, wmma::row_major> af;
            wmma::load_matrix_sync(af, As + (wm * 64 + i * 16) * kLDAh + kk * 16, kLDAh);
#pragma unroll
            for (int j = 0; j < 4; j++)
                wmma::mma_sync(acc[i][j], af, bf[j], acc[i][j]);
        }
    }
}

// ---------------------------------------------------------------------------
// k_base: base[e,b,:] = s @ W1s[e] + b1[e]; e==16 -> gating g1 (relu).
// ---------------------------------------------------------------------------
__global__ __launch_bounds__(256) void k_base(
    const float* __restrict__ s,
    const float* __restrict__ W1, const float* __restrict__ b1,
    const float* __restrict__ Wg1, const float* __restrict__ bg1)
{
    __shared__ float ssm[kB * kEMB];
    __shared__ float red[128][kB];
    const int t = threadIdx.x;
    const int e = blockIdx.y;
    const int jl = t & 127;
    const int half = t >> 7;
    const int j = blockIdx.x * 128 + jl;

    for (int i = t; i < kB * kEMB; i += 256) ssm[i] = s[i];
    __syncthreads();

    const float* __restrict__ W = (e < kNE) ? (W1 + (size_t)e * kW1R * kH1) : Wg1;

    float acc[kB];
#pragma unroll
    for (int b = 0; b < kB; b++) acc[b] = 0.f;

    const int i0 = half * 512;
#pragma unroll 4
    for (int i = i0; i < i0 + 512; i++) {
        const float w = W[(size_t)i * kH1 + j];
#pragma unroll
        for (int b = 0; b < kB; b++) acc[b] += ssm[b * kEMB + i] * w;
    }

    if (half) {
#pragma unroll
        for (int b = 0; b < kB; b++) red[jl][b] = acc[b];
    }
    __syncthreads();
    if (!half) {
#pragma unroll
        for (int b = 0; b < kB; b++) acc[b] += red[jl][b];
        if (e < kNE) {
            const float bias = b1[e * kH1 + j];
#pragma unroll
            for (int b = 0; b < kB; b++)
                g_base[((size_t)e * kB + b) * kH1 + j] = acc[b] + bias;
        } else {
            const float bias = bg1[j];
#pragma unroll
            for (int b = 0; b < kB; b++)
                g_g1[b * kH1 + j] = fmaxf(acc[b] + bias, 0.f);
        }
    }
}

// ---------------------------------------------------------------------------
// k_gate
// ---------------------------------------------------------------------------
__global__ __launch_bounds__(1024) void k_gate(
    const float* __restrict__ Wg2, const float* __restrict__ bg2)
{
    __shared__ float red[1024];
    const int t = threadIdx.x;
    const int b = t >> 7;
    const int rem = t & 127;
    const int kc = rem >> 4;
    const int x = rem & 15;

    float acc = 0.f;
    const int j0 = kc * 256;
#pragma unroll 4
    for (int j = j0; j < j0 + 256; j++)
        acc += g_g1[b * kH1 + j] * Wg2[j * kNE + x];
    red[t] = acc;
    __syncthreads();

    if (t < 128) {
        const int bb = t >> 4;
        const int xx = t & 15;
        float a = bg2[xx];
#pragma unroll
        for (int k = 0; k < 8; k++) a += red[bb * 128 + k * 16 + xx];

        float mx = a;
#pragma unroll
        for (int o = 8; o >= 1; o >>= 1)
            mx = fmaxf(mx, __shfl_xor_sync(0xffffffffu, mx, o, 16));
        const float ev = expf(a - mx);
        float sm = ev;
#pragma unroll
        for (int o = 8; o >= 1; o >>= 1)
            sm += __shfl_xor_sync(0xffffffffu, sm, o, 16);

        g_w[bb * kNE + xx] = ev / sm;
    }
}

// ---------------------------------------------------------------------------
// k_gemm_eo: fused-h split-K per-expert fp16 GEMM, full-height tile 256x128.
// Grid: (4 ntiles, 1, 32 = expert*2 + khalf). K per CTA = 1024, 16 k-tiles.
// ---------------------------------------------------------------------------
__global__ __launch_bounds__(256) void k_gemm_eo(
    const float* __restrict__ W1)
{
    extern __shared__ __align__(16) char smem_raw[];
    __half* smem = reinterpret_cast<__half*>(smem_raw);
    __shared__ float ws[kB];

    const int t = threadIdx.x;
    const int warp = t >> 5;
    const int wm = warp >> 1;   // 0..3
    const int wn = warp & 1;    // 0..1
    const int zz = blockIdx.z, e = zz >> 1, kh = zz & 1;
    const int n0 = blockIdx.x * 128;

    if (t < kB) ws[t] = g_w[t * kNE + e];

    const float* base_e = g_base + (size_t)e * kB * kH1 + kh * 1024;
    const float* w1c_e  = W1 + ((size_t)e * kW1R + kEMB) * kH1 + kh * 1024;
    const __half* B     = g_W2h + (size_t)e * kH1 * kH2 + (size_t)(kh * 1024) * kH2 + n0;

    wmma::fragment<wmma::accumulator, 16, 16, 16, float> acc[4][4];
#pragma unroll
    for (int i = 0; i < 4; i++)
#pragma unroll
        for (int j = 0; j < 4; j++) wmma::fill_fragment(acc[i][j], 0.f);

    __syncthreads();   // ws visible

    constexpr int NT = 1024 / 64;   // 16
    load_B(smem + kAstH, B, kH2, 0, t);
    cp_commit();
    load_A_eo(smem, base_e, w1c_e, ws, 0, t);
    load_B(smem + kStH + kAstH, B, kH2, 64, t);
    cp_commit();
    load_A_eo(smem + kStH, base_e, w1c_e, ws, 64, t);
    __syncthreads();   // A STS of stages 0,1 visible

    for (int it = 0; it < NT; it++) {
        if (it + 1 < NT) cp_wait<1>(); else cp_wait<0>();
        __syncthreads();
        if (it + 2 < NT) {
            __half* nxt = smem + ((it + 2) % 3) * kStH;
            load_B(nxt + kAstH, B, kH2, (it + 2) * 64, t);
            cp_commit();
            load_A_eo(nxt, base_e, w1c_e, ws, (it + 2) * 64, t);
        }
        const __half* stg = smem + (it % 3) * kStH;
        tile_compute(stg, stg + kAstH, wm, wn, acc);
    }

    float* O = g_eo2 + (size_t)zz * kM * kH2 + n0;
#pragma unroll
    for (int i = 0; i < 4; i++)
#pragma unroll
        for (int j = 0; j < 4; j++)
            wmma::store_matrix_sync(O + (size_t)(wm * 64 + i * 16) * kH2 + wn * 64 + j * 16,
                                    acc[i][j], kH2, wmma::mem_row_major);
}

// ---------------------------------------------------------------------------
// k_z: z = half( sum over 32 partial slabs + sum_e w[b,e]*b2[e] ).
// ---------------------------------------------------------------------------
__global__ __launch_bounds__(256) void k_z(const float* __restrict__ b2)
{
    const int idx = blockIdx.x * 256 + threadIdx.x;
    const int n = idx & (kH2 - 1);
    const int m = idx >> 9;
    const int b = m & 7;

    float acc = 0.f;
#pragma unroll
    for (int p = 0; p < 2 * kNE; p++)
        acc += g_eo2[(size_t)p * (kM * kH2) + idx];
#pragma unroll
    for (int e = 0; e < kNE; e++)
        acc += g_w[b * kNE + e] * b2[e * kH2 + n];
    g_zh[idx] = __float2half_rn(acc);
}

// ---------------------------------------------------------------------------
// k_gemm_out: z(256x512 fp16) @ {WAh,WBh}(512x16384 fp16) + bias -> out f32.
// Full-height tile 256x128. Grid: (128 ntiles, 1, 2 mats). 8 k-tiles of 64.
// ---------------------------------------------------------------------------
__global__ __launch_bounds__(256) void k_gemm_out(
    const float* __restrict__ bA, const float* __restrict__ bB,
    float* __restrict__ out)
{
    extern __shared__ __align__(16) char smem_raw[];
    __half* smem = reinterpret_cast<__half*>(smem_raw);

    const int t = threadIdx.x;
    const int warp = t >> 5;
    const int wm = warp >> 1;
    const int wn = warp & 1;
    const int mat = blockIdx.z;
    const int n0 = blockIdx.x * 128;

    const __half* Bw = (mat ? g_WBh : g_WAh) + n0;
    const float* bias = mat ? bB : bA;
    const __half* A = g_zh;

    wmma::fragment<wmma::accumulator, 16, 16, 16, float> acc[4][4];
#pragma unroll
    for (int i = 0; i < 4; i++)
#pragma unroll
        for (int j = 0; j < 4; j++) wmma::fill_fragment(acc[i][j], 0.f);

    constexpr int NT = kH2 / 64;   // 8
    load_A_cp(smem, A, kH2, 0, t);
    load_B(smem + kAstH, Bw, kFO, 0, t);
    cp_commit();
    load_A_cp(smem + kStH, A, kH2, 64, t);
    load_B(smem + kStH + kAstH, Bw, kFO, 64, t);
    cp_commit();

    for (int it = 0; it < NT; it++) {
        if (it + 1 < NT) cp_wait<1>(); else cp_wait<0>();
        __syncthreads();
        if (it + 2 < NT) {
            __half* nxt = smem + ((it + 2) % 3) * kStH;
            load_A_cp(nxt, A, kH2, (it + 2) * 64, t);
            load_B(nxt + kAstH, Bw, kFO, (it + 2) * 64, t);
            cp_commit();
        }
        const __half* stg = smem + (it % 3) * kStH;
        tile_compute(stg, stg + kAstH, wm, wn, acc);
    }

    // Epilogue: stage 256x128 fp32 (stride 132) in smem, add bias, stores.
    __syncthreads();
    float* stage = reinterpret_cast<float*>(smem_raw);   // 256*132*4 = 135168 B
#pragma unroll
    for (int i = 0; i < 4; i++)
#pragma unroll
        for (int j = 0; j < 4; j++)
            wmma::store_matrix_sync(stage + (wm * 64 + i * 16) * 132 + wn * 64 + j * 16,
                                    acc[i][j], 132, wmma::mem_row_major);
    __syncthreads();

    float* O = out + (size_t)mat * kM * kFO + n0;
#pragma unroll
    for (int i = 0; i < 32; i++) {
        const int id = t + i * 256;
        const int r = id >> 5, c4 = (id & 31) * 4;
        float4 v = *reinterpret_cast<const float4*>(stage + r * 132 + c4);
        const float4 bv = *reinterpret_cast<const float4*>(bias + n0 + c4);
        v.x += bv.x; v.y += bv.y; v.z += bv.z; v.w += bv.w;
        *reinterpret_cast<float4*>(O + (size_t)r * kFO + c4) = v;
    }
}

// ---------------------------------------------------------------------------
// kernel_launch
// ---------------------------------------------------------------------------
extern "C" void kernel_launch(void* const* d_in, const int* in_sizes, int n_in,
                              void* d_out, int out_size)
{
    const float* s   = (const float*)d_in[0];
    const float* Wg1 = (const float*)d_in[1];
    const float* bg1 = (const float*)d_in[2];
    const float* Wg2 = (const float*)d_in[3];
    const float* bg2 = (const float*)d_in[4];
    const float* W1  = (const float*)d_in[5];
    const float* b1  = (const float*)d_in[6];
    const float* W2  = (const float*)d_in[7];
    const float* b2  = (const float*)d_in[8];
    const float* WA  = (const float*)d_in[9];
    const float* bA  = (const float*)d_in[10];
    const float* WB  = (const float*)d_in[11];
    const float* bB  = (const float*)d_in[12];
    float* out = (float*)d_out;

    cudaFuncSetAttribute(k_gemm_eo,  cudaFuncAttributeMaxDynamicSharedMemorySize, kSmemGemm);
    cudaFuncSetAttribute(k_gemm_out, cudaFuncAttributeMaxDynamicSharedMemorySize, kSmemGemm);

    __half* d_W2h; cudaGetSymbolAddress((void**)&d_W2h, g_W2h);
    __half* d_WAh; cudaGetSymbolAddress((void**)&d_WAh, g_WAh);
    __half* d_WBh; cudaGetSymbolAddress((void**)&d_WBh, g_WBh);

    const int nW2 = kNE * kH1 * kH2;   // 16,777,216
    const int nWO = kH2 * kFO;         //  8,388,608
    k_cvt<<<nW2 / 8 / 256, 256>>>(W2, d_W2h, nW2);
    k_cvt<<<nWO / 8 / 256, 256>>>(WA, d_WAh, nWO);
    k_cvt<<<nWO / 8 / 256, 256>>>(WB, d_WBh, nWO);

    k_base<<<dim3(kH1 / 128, kNE + 1), 256>>>(s, W1, b1, Wg1, bg1);
    k_gate<<<1, 1024>>>(Wg2, bg2);
    k_gemm_eo<<<dim3(kH2 / 128, 1, 2 * kNE), 256, kSmemGemm>>>(W1);
    k_z<<<(kM * kH2) / 256, 256>>>(b2);
    k_gemm_out<<<dim3(kFO / 128, 1, 2), 256, kSmemGemm>>>(bA, bB, out);
}

// round 11
// speedup vs baseline: 1.6930x; 1.1187x over previous
#include <cuda_runtime.h>
#include <cuda_fp16.h>
#include <cstdint>
#include <mma.h>

using namespace nvcuda;

// ---------------------------------------------------------------------------
// MoE HyperModel, round 10:
//  - k_base: float4 weight loads + 4-way split-K (MLP fix, DRAM-bound).
//  - GEMMs: fp16 wmma, weights converted fp32->fp16 inside the loaders
//    (register-stage pipeline; no separate convert kernels).
// ---------------------------------------------------------------------------

namespace {
constexpr int kEMB = 1024;
constexpr int kCTX = 32;
constexpr int kNE  = 16;
constexpr int kH1  = 2048;
constexpr int kH2  = 512;
constexpr int kB   = 8;
constexpr int kM   = kCTX * kB;     // 256
constexpr int kFO  = 16384;
constexpr int kW1R = kEMB + kCTX;   // 1056

constexpr int kLDAh = 72;    // smem A stride (halves): 256 rows x 64 k (+pad)
constexpr int kLDBh = 136;   // smem B stride (halves): 64 rows x 128 n (+pad)
constexpr int kAstH = 256 * kLDAh;        // 18432 halves
constexpr int kBstH = 64 * kLDBh;         // 8704 halves
constexpr int kStH  = kAstH + kBstH;      // 27136 halves
constexpr int kSmemGemm = 2 * kStH * 2;   // 108544 bytes (2 stages)
}

// Scratch (static device arrays -- allocation-free).
__device__ float  g_g1[kB * kH1];
__device__ float  g_w[kB * kNE];
__device__ float  g_base[kNE * kB * kH1];
__device__ float  g_eo2[(size_t)2 * kNE * kM * kH2];   // split-K partials
__device__ __half g_zh[kM * kH2];                      // z in fp16

// --------------------------- reg-stage loaders ------------------------------
// B (fp32 source -> fp16 regs): 64 k-rows x 128 n. 8 chunks/thread.
__device__ __forceinline__ void ldB32(uint2* bR, const float* B, int ldb,
                                      int kt, int t)
{
#pragma unroll
    for (int i = 0; i < 8; i++) {
        const int id = t + i * 256;
        const int r = id >> 5, c4 = (id & 31) * 4;
        const float4 v = *reinterpret_cast<const float4*>(B + (size_t)(kt + r) * ldb + c4);
        __half2 h0 = __floats2half2_rn(v.x, v.y);
        __half2 h1 = __floats2half2_rn(v.z, v.w);
        bR[i].x = *reinterpret_cast<unsigned*>(&h0);
        bR[i].y = *reinterpret_cast<unsigned*>(&h1);
    }
}
__device__ __forceinline__ void stsB(__half* Bs, const uint2* bR, int t)
{
#pragma unroll
    for (int i = 0; i < 8; i++) {
        const int id = t + i * 256;
        const int r = id >> 5, c4 = (id & 31) * 4;
        *reinterpret_cast<uint2*>(Bs + r * kLDBh + c4) = bR[i];
    }
}
// A (eo, fused h): half( w[b] * relu(base[b][k] + W1c[c][k]) ). 8 chunks/thr.
__device__ __forceinline__ void ldA_eo(uint4* aR,
                                       const float* base_e, const float* w1c_e,
                                       const float* ws, int kt, int t)
{
#pragma unroll
    for (int i = 0; i < 8; i++) {
        const int id = t + i * 256;
        const int m = id >> 3, kc = (id & 7) * 8;
        const int b = m & 7, c = m >> 3;
        const float* bp = base_e + (size_t)b * kH1 + kt + kc;
        const float* wp = w1c_e  + (size_t)c * kH1 + kt + kc;
        const float4 b0 = *reinterpret_cast<const float4*>(bp);
        const float4 b1 = *reinterpret_cast<const float4*>(bp + 4);
        const float4 w0 = *reinterpret_cast<const float4*>(wp);
        const float4 w1 = *reinterpret_cast<const float4*>(wp + 4);
        const float w = ws[b];
        __half2 h0 = __floats2half2_rn(w * fmaxf(b0.x + w0.x, 0.f), w * fmaxf(b0.y + w0.y, 0.f));
        __half2 h1 = __floats2half2_rn(w * fmaxf(b0.z + w0.z, 0.f), w * fmaxf(b0.w + w0.w, 0.f));
        __half2 h2 = __floats2half2_rn(w * fmaxf(b1.x + w1.x, 0.f), w * fmaxf(b1.y + w1.y, 0.f));
        __half2 h3 = __floats2half2_rn(w * fmaxf(b1.z + w1.z, 0.f), w * fmaxf(b1.w + w1.w, 0.f));
        aR[i].x = *reinterpret_cast<unsigned*>(&h0);
        aR[i].y = *reinterpret_cast<unsigned*>(&h1);
        aR[i].z = *reinterpret_cast<unsigned*>(&h2);
        aR[i].w = *reinterpret_cast<unsigned*>(&h3);
    }
}
// A (out GEMM): fp16 source (g_zh). 8 chunks/thread.
__device__ __forceinline__ void ldA16(uint4* aR, const __half* A, int lda,
                                      int kt, int t)
{
#pragma unroll
    for (int i = 0; i < 8; i++) {
        const int id = t + i * 256;
        const int m = id >> 3, kc = (id & 7) * 8;
        aR[i] = *reinterpret_cast<const uint4*>(A + (size_t)m * lda + kt + kc);
    }
}
__device__ __forceinline__ void stsA(__half* As, const uint4* aR, int t)
{
#pragma unroll
    for (int i = 0; i < 8; i++) {
        const int id = t + i * 256;
        const int m = id >> 3, kc = (id & 7) * 8;
        *reinterpret_cast<uint4*>(As + m * kLDAh + kc) = aR[i];
    }
}

// --------------------------- compute: warp 64x64, k-tile 64 ----------------
__device__ __forceinline__ void tile_compute(
    const __half* As, const __half* Bs, int wm, int wn,
    wmma::fragment<wmma::accumulator, 16, 16, 16, float> (&acc)[4][4])
{
#pragma unroll
    for (int kk = 0; kk < 4; kk++) {
        wmma::fragment<wmma::matrix_b, 16, 16, 16, __half, wmma::row_major> bf[4];
#pragma unroll
        for (int j = 0; j < 4; j++)
            wmma::load_matrix_sync(bf[j], Bs + (kk * 16) * kLDBh + wn * 64 + j * 16, kLDBh);
#pragma unroll
        for (int i = 0; i < 4; i++) {
            wmma::fragment<wmma::matrix_a, 16, 16, 16, __half, wmma::row_major> af;
            wmma::load_matrix_sync(af, As + (wm * 64 + i * 16) * kLDAh + kk * 16, kLDAh);
#pragma unroll
            for (int j = 0; j < 4; j++)
                wmma::mma_sync(acc[i][j], af, bf[j], acc[i][j]);
        }
    }
}

// ---------------------------------------------------------------------------
// k_base: base[e,b,:] = s @ W1s[e] + b1[e]; e==16 -> gating g1 (relu).
// float4 weight loads, 4 K-slices of 256, smem reduce. Grid (8, 17).
// ---------------------------------------------------------------------------
__global__ __launch_bounds__(256) void k_base(
    const float* __restrict__ s,
    const float* __restrict__ W1, const float* __restrict__ b1,
    const float* __restrict__ Wg1, const float* __restrict__ bg1)
{
    __shared__ float sh[kB * kEMB];   // 32 KB: s, then reduction buffer
    const int t = threadIdx.x;
    const int e = blockIdx.y;
    const int q = t & 63;             // j-group (4 cols each)
    const int slice = t >> 6;         // K-slice 0..3
    const int j = blockIdx.x * 256 + q * 4;

    for (int i = t; i < kB * kEMB; i += 256) sh[i] = s[i];
    __syncthreads();

    const float* __restrict__ W = (e < kNE) ? (W1 + (size_t)e * kW1R * kH1) : Wg1;

    float acc[kB][4];
#pragma unroll
    for (int b = 0; b < kB; b++)
#pragma unroll
        for (int c = 0; c < 4; c++) acc[b][c] = 0.f;

    const int i0 = slice * 256;
#pragma unroll 8
    for (int i = i0; i < i0 + 256; i++) {
        const float4 wv = *reinterpret_cast<const float4*>(W + (size_t)i * kH1 + j);
#pragma unroll
        for (int b = 0; b < kB; b++) {
            const float sv = sh[b * kEMB + i];
            acc[b][0] += sv * wv.x;
            acc[b][1] += sv * wv.y;
            acc[b][2] += sv * wv.z;
            acc[b][3] += sv * wv.w;
        }
    }

    __syncthreads();   // done with s; reuse sh as reduction buffer
    // red layout: red[(b*4+c)*192 + (slice-1)*64 + q]  (conflict-free)
    if (slice > 0) {
#pragma unroll
        for (int b = 0; b < kB; b++)
#pragma unroll
            for (int c = 0; c < 4; c++)
                sh[(b * 4 + c) * 192 + (slice - 1) * 64 + q] = acc[b][c];
    }
    __syncthreads();
    if (slice == 0) {
#pragma unroll
        for (int sl = 0; sl < 3; sl++)
#pragma unroll
            for (int b = 0; b < kB; b++)
#pragma unroll
                for (int c = 0; c < 4; c++)
                    acc[b][c] += sh[(b * 4 + c) * 192 + sl * 64 + q];

        if (e < kNE) {
            const float4 bias = *reinterpret_cast<const float4*>(b1 + e * kH1 + j);
#pragma unroll
            for (int b = 0; b < kB; b++) {
                float4 o;
                o.x = acc[b][0] + bias.x; o.y = acc[b][1] + bias.y;
                o.z = acc[b][2] + bias.z; o.w = acc[b][3] + bias.w;
                *reinterpret_cast<float4*>(&g_base[((size_t)e * kB + b) * kH1 + j]) = o;
            }
        } else {
            const float4 bias = *reinterpret_cast<const float4*>(bg1 + j);
#pragma unroll
            for (int b = 0; b < kB; b++) {
                float4 o;
                o.x = fmaxf(acc[b][0] + bias.x, 0.f);
                o.y = fmaxf(acc[b][1] + bias.y, 0.f);
                o.z = fmaxf(acc[b][2] + bias.z, 0.f);
                o.w = fmaxf(acc[b][3] + bias.w, 0.f);
                *reinterpret_cast<float4*>(&g_g1[b * kH1 + j]) = o;
            }
        }
    }
}

// ---------------------------------------------------------------------------
// k_gate
// ---------------------------------------------------------------------------
__global__ __launch_bounds__(1024) void k_gate(
    const float* __restrict__ Wg2, const float* __restrict__ bg2)
{
    __shared__ float red[1024];
    const int t = threadIdx.x;
    const int b = t >> 7;
    const int rem = t & 127;
    const int kc = rem >> 4;
    const int x = rem & 15;

    float acc = 0.f;
    const int j0 = kc * 256;
#pragma unroll 4
    for (int j = j0; j < j0 + 256; j++)
        acc += g_g1[b * kH1 + j] * Wg2[j * kNE + x];
    red[t] = acc;
    __syncthreads();

    if (t < 128) {
        const int bb = t >> 4;
        const int xx = t & 15;
        float a = bg2[xx];
#pragma unroll
        for (int k = 0; k < 8; k++) a += red[bb * 128 + k * 16 + xx];

        float mx = a;
#pragma unroll
        for (int o = 8; o >= 1; o >>= 1)
            mx = fmaxf(mx, __shfl_xor_sync(0xffffffffu, mx, o, 16));
        const float ev = expf(a - mx);
        float sm = ev;
#pragma unroll
        for (int o = 8; o >= 1; o >>= 1)
            sm += __shfl_xor_sync(0xffffffffu, sm, o, 16);

        g_w[bb * kNE + xx] = ev / sm;
    }
}

// ---------------------------------------------------------------------------
// k_gemm_eo: fused-h split-K per-expert fp16 GEMM, tile 256x128, k-tile 64.
// B converted fp32->fp16 in the loader. Grid: (4, 1, 32 = e*2 + kh).
// ---------------------------------------------------------------------------
__global__ __launch_bounds__(256) void k_gemm_eo(
    const float* __restrict__ W1, const float* __restrict__ W2)
{
    extern __shared__ __align__(16) char smem_raw[];
    __half* smem = reinterpret_cast<__half*>(smem_raw);
    __shared__ float ws[kB];

    const int t = threadIdx.x;
    const int warp = t >> 5;
    const int wm = warp >> 1;   // 0..3
    const int wn = warp & 1;    // 0..1
    const int zz = blockIdx.z, e = zz >> 1, kh = zz & 1;
    const int n0 = blockIdx.x * 128;

    if (t < kB) ws[t] = g_w[t * kNE + e];

    const float* base_e = g_base + (size_t)e * kB * kH1 + kh * 1024;
    const float* w1c_e  = W1 + ((size_t)e * kW1R + kEMB) * kH1 + kh * 1024;
    const float* Bsrc   = W2 + (size_t)e * kH1 * kH2 + (size_t)(kh * 1024) * kH2 + n0;

    wmma::fragment<wmma::accumulator, 16, 16, 16, float> acc[4][4];
#pragma unroll
    for (int i = 0; i < 4; i++)
#pragma unroll
        for (int j = 0; j < 4; j++) wmma::fill_fragment(acc[i][j], 0.f);

    __syncthreads();   // ws visible

    constexpr int NT = 1024 / 64;   // 16
    uint4 aR[8];
    uint2 bR[8];
    ldB32(bR, Bsrc, kH2, 0, t);
    ldA_eo(aR, base_e, w1c_e, ws, 0, t);
    stsB(smem + kAstH, bR, t);
    stsA(smem, aR, t);
    ldB32(bR, Bsrc, kH2, 64, t);
    ldA_eo(aR, base_e, w1c_e, ws, 64, t);
    __syncthreads();

    for (int it = 0; it < NT; it++) {
        __half* cur = smem + (it & 1) * kStH;
        if (it + 1 < NT) {
            __half* nxt = smem + ((it + 1) & 1) * kStH;
            stsB(nxt + kAstH, bR, t);
            stsA(nxt, aR, t);
        }
        if (it + 2 < NT) {
            ldB32(bR, Bsrc, kH2, (it + 2) * 64, t);
            ldA_eo(aR, base_e, w1c_e, ws, (it + 2) * 64, t);
        }
        tile_compute(cur, cur + kAstH, wm, wn, acc);
        __syncthreads();
    }

    float* O = g_eo2 + (size_t)zz * kM * kH2 + n0;
#pragma unroll
    for (int i = 0; i < 4; i++)
#pragma unroll
        for (int j = 0; j < 4; j++)
            wmma::store_matrix_sync(O + (size_t)(wm * 64 + i * 16) * kH2 + wn * 64 + j * 16,
                                    acc[i][j], kH2, wmma::mem_row_major);
}

// ---------------------------------------------------------------------------
// k_z: z = half( sum over 32 partial slabs + sum_e w[b,e]*b2[e] ).
// ---------------------------------------------------------------------------
__global__ __launch_bounds__(256) void k_z(const float* __restrict__ b2)
{
    const int idx = blockIdx.x * 256 + threadIdx.x;
    const int n = idx & (kH2 - 1);
    const int m = idx >> 9;
    const int b = m & 7;

    float acc = 0.f;
#pragma unroll
    for (int p = 0; p < 2 * kNE; p++)
        acc += g_eo2[(size_t)p * (kM * kH2) + idx];
#pragma unroll
    for (int e = 0; e < kNE; e++)
        acc += g_w[b * kNE + e] * b2[e * kH2 + n];
    g_zh[idx] = __float2half_rn(acc);
}

// ---------------------------------------------------------------------------
// k_gemm_out: z(256x512 fp16) @ {WA,WB}(512x16384 fp32->fp16) + bias -> out.
// Tile 256x128, 8 k-tiles of 64. Two-pass smem epilogue. Grid (128, 1, 2).
// ---------------------------------------------------------------------------
__global__ __launch_bounds__(256) void k_gemm_out(
    const float* __restrict__ WA, const float* __restrict__ bA,
    const float* __restrict__ WB, const float* __restrict__ bB,
    float* __restrict__ out)
{
    extern __shared__ __align__(16) char smem_raw[];
    __half* smem = reinterpret_cast<__half*>(smem_raw);

    const int t = threadIdx.x;
    const int warp = t >> 5;
    const int wm = warp >> 1;
    const int wn = warp & 1;
    const int mat = blockIdx.z;
    const int n0 = blockIdx.x * 128;

    const float* Bsrc = (mat ? WB : WA) + n0;
    const float* bias = mat ? bB : bA;
    const __half* A = g_zh;

    wmma::fragment<wmma::accumulator, 16, 16, 16, float> acc[4][4];
#pragma unroll
    for (int i = 0; i < 4; i++)
#pragma unroll
        for (int j = 0; j < 4; j++) wmma::fill_fragment(acc[i][j], 0.f);

    constexpr int NT = kH2 / 64;   // 8
    uint4 aR[8];
    uint2 bR[8];
    ldB32(bR, Bsrc, kFO, 0, t);
    ldA16(aR, A, kH2, 0, t);
    stsB(smem + kAstH, bR, t);
    stsA(smem, aR, t);
    ldB32(bR, Bsrc, kFO, 64, t);
    ldA16(aR, A, kH2, 64, t);
    __syncthreads();

    for (int it = 0; it < NT; it++) {
        __half* cur = smem + (it & 1) * kStH;
        if (it + 1 < NT) {
            __half* nxt = smem + ((it + 1) & 1) * kStH;
            stsB(nxt + kAstH, bR, t);
            stsA(nxt, aR, t);
        }
        if (it + 2 < NT) {
            ldB32(bR, Bsrc, kFO, (it + 2) * 64, t);
            ldA16(aR, A, kH2, (it + 2) * 64, t);
        }
        tile_compute(cur, cur + kAstH, wm, wn, acc);
        __syncthreads();
    }

    // Epilogue: two passes of 128 rows through a 128x128 fp32 smem stage.
    float* stage = reinterpret_cast<float*>(smem_raw);   // 128*132*4 = 67584 B
    float* O = out + (size_t)mat * kM * kFO + n0;
    __syncthreads();
#pragma unroll
    for (int p = 0; p < 2; p++) {
        if ((wm >> 1) == p) {
#pragma unroll
            for (int i = 0; i < 4; i++)
#pragma unroll
                for (int j = 0; j < 4; j++)
                    wmma::store_matrix_sync(
                        stage + ((wm & 1) * 64 + i * 16) * 132 + wn * 64 + j * 16,
                        acc[i][j], 132, wmma::mem_row_major);
        }
        __syncthreads();
#pragma unroll
        for (int i = 0; i < 16; i++) {
            const int id = t + i * 256;
            const int r = id >> 5, c4 = (id & 31) * 4;
            float4 v = *reinterpret_cast<const float4*>(stage + r * 132 + c4);
            const float4 bv = *reinterpret_cast<const float4*>(bias + n0 + c4);
            v.x += bv.x; v.y += bv.y; v.z += bv.z; v.w += bv.w;
            *reinterpret_cast<float4*>(O + (size_t)(p * 128 + r) * kFO + c4) = v;
        }
        __syncthreads();
    }
}

// ---------------------------------------------------------------------------
// kernel_launch
// ---------------------------------------------------------------------------
extern "C" void kernel_launch(void* const* d_in, const int* in_sizes, int n_in,
                              void* d_out, int out_size)
{
    const float* s   = (const float*)d_in[0];
    const float* Wg1 = (const float*)d_in[1];
    const float* bg1 = (const float*)d_in[2];
    const float* Wg2 = (const float*)d_in[3];
    const float* bg2 = (const float*)d_in[4];
    const float* W1  = (const float*)d_in[5];
    const float* b1  = (const float*)d_in[6];
    const float* W2  = (const float*)d_in[7];
    const float* b2  = (const float*)d_in[8];
    const float* WA  = (const float*)d_in[9];
    const float* bA  = (const float*)d_in[10];
    const float* WB  = (const float*)d_in[11];
    const float* bB  = (const float*)d_in[12];
    float* out = (float*)d_out;

    cudaFuncSetAttribute(k_gemm_eo,  cudaFuncAttributeMaxDynamicSharedMemorySize, kSmemGemm);
    cudaFuncSetAttribute(k_gemm_out, cudaFuncAttributeMaxDynamicSharedMemorySize, kSmemGemm);

    k_base<<<dim3(kH1 / 256, kNE + 1), 256>>>(s, W1, b1, Wg1, bg1);
    k_gate<<<1, 1024>>>(Wg2, bg2);
    k_gemm_eo<<<dim3(kH2 / 128, 1, 2 * kNE), 256, kSmemGemm>>>(W1, W2);
    k_z<<<(kM * kH2) / 256, 256>>>(b2);
    k_gemm_out<<<dim3(kFO / 128, 1, 2), 256, kSmemGemm>>>(WA, bA, WB, bB, out);
}